// round 17
// baseline (speedup 1.0000x reference)
#include <cuda_runtime.h>
#include <math.h>

#define NMAX 10000
#define EMAX 160000
#define TBLM 1024
typedef unsigned long long ull;

// device scratch (no runtime allocation)
__device__ __align__(16) float g_p0[NMAX * 16];
__device__ __align__(16) float g_p1[NMAX * 24];
__device__ float g_z[NMAX];
__device__ __align__(16) float g_hk[(TBLM + 1) * 16];
__device__ __align__(16) float g_hv[(TBLM + 1) * 16];
__device__ __align__(16) float g_Mk[(TBLM + 1) * 576];  // M(d)[j] = hk(d) . Wk2col_j
__device__ __align__(16) float g_Mv[(TBLM + 1) * 576];
// edge sort (by d-bin) scratch; g_cnt zero-init at load, re-zeroed by normalize each launch
__device__ int g_cnt[TBLM];
__device__ int g_off[TBLM];
__device__ int g_start[TBLM];
__device__ int g_src[EMAX];
__device__ int g_dst[EMAX];
__device__ __align__(16) float4 g_sea[EMAX];
__device__ float g_sd[EMAX];

// ---------- packed f32x2 primitives ----------
__device__ __forceinline__ ull pk2(float a) {
    ull r; asm("mov.b64 %0, {%1,%1};" : "=l"(r) : "f"(a)); return r;
}
__device__ __forceinline__ ull pk(float a, float b) {
    ull r; asm("mov.b64 %0, {%1,%2};" : "=l"(r) : "f"(a), "f"(b)); return r;
}
__device__ __forceinline__ float2 upk(ull a) {
    float2 f; asm("mov.b64 {%0,%1}, %2;" : "=f"(f.x), "=f"(f.y) : "l"(a)); return f;
}
__device__ __forceinline__ ull f2fma(ull a, ull b, ull c) {
    ull d; asm("fma.rn.f32x2 %0, %1, %2, %3;" : "=l"(d) : "l"(a), "l"(b), "l"(c)); return d;
}
__device__ __forceinline__ ull f2mul(ull a, ull b) {
    ull d; asm("mul.rn.f32x2 %0, %1, %2;" : "=l"(d) : "l"(a), "l"(b)); return d;
}
__device__ __forceinline__ ull f2add(ull a, ull b) {
    ull d; asm("add.rn.f32x2 %0, %1, %2;" : "=l"(d) : "l"(a), "l"(b)); return d;
}
// vector reduction atomic: out[0..3] += {a,b,c,d} (16B-aligned)
__device__ __forceinline__ void red4(float* p, float a, float b, float c, float d) {
    asm volatile("red.global.add.v4.f32 [%0], {%1,%2,%3,%4};"
                 :: "l"(p), "f"(a), "f"(b), "f"(c), "f"(d) : "memory");
}
// dot of 8 packed h with 4 ulonglong2 (16 floats)
__device__ __forceinline__ ull dot8c(const ull h[8], ulonglong2 c0, ulonglong2 c1,
                                     ulonglong2 c2, ulonglong2 c3) {
    ull s0 = f2mul(h[0], c0.x), s1 = f2mul(h[1], c0.y);
    s0 = f2fma(h[2], c1.x, s0); s1 = f2fma(h[3], c1.y, s1);
    s0 = f2fma(h[4], c2.x, s0); s1 = f2fma(h[5], c2.y, s1);
    s0 = f2fma(h[6], c3.x, s0); s1 = f2fma(h[7], c3.y, s1);
    return f2add(s0, s1);
}

__device__ __forceinline__ void ld16(float o[16], const float* __restrict__ p) {
    const float4* p4 = reinterpret_cast<const float4*>(p);
    float4 t0 = p4[0], t1 = p4[1], t2 = p4[2], t3 = p4[3];
    o[0] = t0.x; o[1] = t0.y; o[2] = t0.z; o[3] = t0.w;
    o[4] = t1.x; o[5] = t1.y; o[6] = t1.z; o[7] = t1.w;
    o[8] = t2.x; o[9] = t2.y; o[10] = t2.z; o[11] = t2.w;
    o[12] = t3.x; o[13] = t3.y; o[14] = t3.z; o[15] = t3.w;
}
__device__ __forceinline__ void ld24(float o[24], const float* __restrict__ p) {
    const float4* p4 = reinterpret_cast<const float4*>(p);
    #pragma unroll
    for (int k = 0; k < 6; ++k) {
        float4 t = p4[k];
        o[4 * k] = t.x; o[4 * k + 1] = t.y; o[4 * k + 2] = t.z; o[4 * k + 3] = t.w;
    }
}

// -------- stage 1: radial h rows + edge d-bin histogram (g_cnt pre-zeroed)
__global__ void build_h_hist(const float* __restrict__ Wk1, const float* __restrict__ Wv1,
                             const float* __restrict__ amf, int E) {
    int i = blockIdx.x * 256 + threadIdx.x;
    if (i < E) {
        int b = (int)(amf[i] * ((float)TBLM * 0.125f));
        if (b < 0) b = 0;
        if (b > TBLM - 1) b = TBLM - 1;
        atomicAdd(&g_cnt[b], 1);
    }
    if (i > TBLM) return;
    float d = (float)i * (8.0f / (float)TBLM);
    float emb[16];
    #pragma unroll
    for (int b = 0; b < 16; ++b) {
        float cb = 0.47058824f * (float)(b + 1);
        float diff = (d - cb) * 2.125f;
        float q = 1.0f - diff * diff;
        emb[b] = (q > 0.f) ? 33.7342930f * expf(-2.0f / q) : 0.f;
    }
    #pragma unroll
    for (int c = 0; c < 16; ++c) {
        float sk = 0.f, sv = 0.f;
        #pragma unroll
        for (int b = 0; b < 16; ++b) {
            sk = fmaf(emb[b], Wk1[b * 16 + c], sk);
            sv = fmaf(emb[b], Wv1[b * 16 + c], sv);
        }
        sk *= 0.25f; sv *= 0.25f;
        g_hk[i * 16 + c] = sk / (1.f + expf(-sk));
        g_hv[i * 16 + c] = sv / (1.f + expf(-sv));
    }
}

// -------- stage 2: exclusive scan of bins (writes cursor g_off + stable g_start)
__global__ __launch_bounds__(1024) void scan_kernel(int n) {
    __shared__ int part[1024];
    int t = threadIdx.x;
    int chunk = (n + 1023) / 1024;
    int base = t * chunk;
    int s = 0;
    for (int i = 0; i < chunk; ++i) {
        int j = base + i;
        if (j < n) s += g_cnt[j];
    }
    part[t] = s;
    __syncthreads();
    for (int off = 1; off < 1024; off <<= 1) {
        int v = (t >= off) ? part[t - off] : 0;
        __syncthreads();
        part[t] += v;
        __syncthreads();
    }
    int run = (t > 0) ? part[t - 1] : 0;
    for (int i = 0; i < chunk; ++i) {
        int j = base + i;
        if (j < n) {
            int c = g_cnt[j];
            g_off[j] = run;
            g_start[j] = run;
            run += c;
        }
    }
}

// -------- stage 3 (mega): scatter + node_prep + build_M by block role
__global__ __launch_bounds__(256) void mega_kernel(
    const float* __restrict__ x, const int* __restrict__ ei,
    const float* __restrict__ ea, const float* __restrict__ amf,
    const float* __restrict__ Wq0, const float* __restrict__ Wq1,
    const float* __restrict__ Wd0, const float* __restrict__ Wd1,
    const float* __restrict__ Wk2, const float* __restrict__ Wv2,
    float* __restrict__ out, int n, int E, int nbScat, int nbNode) {
    int b = blockIdx.x;
    int t = threadIdx.x;
    if (b < nbScat) {
        int e = b * 256 + t;
        if (e >= E) return;
        float d = amf[e];
        int bin = (int)(d * ((float)TBLM * 0.125f));
        if (bin < 0) bin = 0;
        if (bin > TBLM - 1) bin = TBLM - 1;
        int pos = atomicAdd(&g_off[bin], 1);
        g_src[pos] = ei[e];
        g_dst[pos] = ei[E + e];
        g_sea[pos] = reinterpret_cast<const float4*>(ea)[e];
        g_sd[pos] = d;
        return;
    }
    if (b < nbScat + nbNode) {
        __shared__ float C0[256];
        __shared__ float C1[64];
        {
            int u = t >> 4, v = t & 15;
            float s = 0.f;
            #pragma unroll
            for (int w = 0; w < 16; ++w) s = fmaf(Wq0[u * 16 + w], Wd0[w * 16 + v], s);
            C0[t] = s * 0.25f;
        }
        if (t < 64) {
            int u = t >> 3, v = t & 7;
            float s = 0.f;
            #pragma unroll
            for (int w = 0; w < 8; ++w) s = fmaf(Wq1[u * 8 + w], Wd1[w * 8 + v], s);
            C1[t] = s * 0.2041241452f;  // 1/(sqrt(8)*sqrt(3))
        }
        __syncthreads();
        int i = (b - nbScat) * 256 + t;
        if (i >= n) return;
        float x0[16];
        #pragma unroll
        for (int u = 0; u < 16; ++u) x0[u] = x[i * 40 + u];
        #pragma unroll
        for (int v = 0; v < 16; ++v) {
            float s = 0.f;
            #pragma unroll
            for (int u = 0; u < 16; ++u) s = fmaf(x0[u], C0[u * 16 + v], s);
            g_p0[i * 16 + v] = s;
        }
        float x1[24];
        #pragma unroll
        for (int k = 0; k < 24; ++k) x1[k] = x[i * 40 + 16 + k];
        #pragma unroll
        for (int v = 0; v < 8; ++v) {
            #pragma unroll
            for (int c = 0; c < 3; ++c) {
                float s = 0.f;
                #pragma unroll
                for (int u = 0; u < 8; ++u) s = fmaf(x1[u * 3 + c], C1[u * 8 + v], s);
                g_p1[i * 24 + v * 3 + c] = s;
            }
        }
        g_z[i] = 0.f;
        float4 z4 = make_float4(0.f, 0.f, 0.f, 0.f);
        float4* o4 = reinterpret_cast<float4*>(out + i * 40);
        #pragma unroll
        for (int m = 0; m < 10; ++m) o4[m] = z4;
        return;
    }
    // ---- build_M
    int idx = (b - nbScat - nbNode) * 256 + t;
    int row = idx / 288;
    if (row > TBLM) return;
    int rem = idx % 288;
    int tbl = rem / 144;
    int j4 = (rem % 144) * 4;
    const float* h = (tbl ? g_hv : g_hk) + row * 16;
    const float* W = tbl ? Wv2 : Wk2;
    float a0 = 0.f, a1 = 0.f, a2 = 0.f, a3 = 0.f;
    #pragma unroll
    for (int c = 0; c < 16; ++c) {
        float hc = h[c];
        const float4 w = *reinterpret_cast<const float4*>(W + c * 576 + j4);
        a0 = fmaf(hc, w.x, a0); a1 = fmaf(hc, w.y, a1);
        a2 = fmaf(hc, w.z, a2); a3 = fmaf(hc, w.w, a3);
    }
    float* dst = (tbl ? g_Mv : g_Mk) + row * 576 + j4;
    *reinterpret_cast<float4*>(dst) = make_float4(a0, a1, a2, a3);
}

// -------- fused edge kernel: ONE BLOCK PER d-BIN; M rows staged in smem (broadcast reads)
__global__ __launch_bounds__(96, 5) void edge_fused(
    const float* __restrict__ x, float* __restrict__ out, int E) {
    __shared__ __align__(16) float sM[2304];  // [Mk row b | Mk row b+1 | Mv row b | Mv row b+1]
    int b = blockIdx.x;
    int t = threadIdx.x;
    {
        float4* s4 = reinterpret_cast<float4*>(sM);
        const float4* mk4 = reinterpret_cast<const float4*>(g_Mk + b * 576);
        const float4* mv4 = reinterpret_cast<const float4*>(g_Mv + b * 576);
        for (int i = t; i < 288; i += 96) s4[i] = mk4[i];          // rows b, b+1 contiguous
        for (int i = t; i < 288; i += 96) s4[288 + i] = mv4[i];
    }
    int start = g_start[b];
    int end = (b + 1 < TBLM) ? g_start[b + 1] : E;
    __syncthreads();

    for (int e = start + t; e < end; e += 96) {
        int src = g_src[e], dst = g_dst[e];
        float4 sh = g_sea[e];
        float d = g_sd[e];

        float x0[16]; ld16(x0, x + src * 40);
        float x1s[24], dd[8];
        {
            float tt[24]; ld24(tt, x + src * 40 + 16);
            #pragma unroll
            for (int u = 0; u < 8; ++u) {
                dd[u] = (tt[3 * u] * sh.y + tt[3 * u + 1] * sh.z + tt[3 * u + 2] * sh.w) * 0.57735027f;
                x1s[3 * u] = tt[3 * u] * sh.x;
                x1s[3 * u + 1] = tt[3 * u + 1] * sh.x;
                x1s[3 * u + 2] = tt[3 * u + 2] * sh.x;
            }
        }
        float f = d * ((float)TBLM * 0.125f) - (float)b;
        if (f < 0.f) f = 0.f;
        if (f > 1.f) f = 1.f;
        float omf = 1.0f - f;
        ull fp = pk2(f), omfp = pk2(omf);

        // ---- score: dual acc chains over smem rows
        float ev;
        {
            ull p0p[8];
            {
                float p0[16]; ld16(p0, g_p0 + dst * 16);
                #pragma unroll
                for (int k = 0; k < 8; ++k) p0p[k] = pk(p0[2 * k], p0[2 * k + 1]);
            }
            float p1[24]; ld24(p1, g_p1 + dst * 24);
            ull rp[4];
            #pragma unroll
            for (int k = 0; k < 4; ++k) {
                float r0 = p1[6 * k] * sh.y + p1[6 * k + 1] * sh.z + p1[6 * k + 2] * sh.w;
                float r1 = p1[6 * k + 3] * sh.y + p1[6 * k + 4] * sh.z + p1[6 * k + 5] * sh.w;
                rp[k] = pk(r0, r1);
            }
            const ulonglong2* L = reinterpret_cast<const ulonglong2*>(sM);
            const ulonglong2* H = L + 144;
            ull aL = pk2(0.f), aH = pk2(0.f);
            #pragma unroll
            for (int u = 0; u < 16; ++u) {
                ull g = pk2(x0[u] * sh.x);
                aL = f2fma(g, dot8c(p0p, L[u * 4], L[u * 4 + 1], L[u * 4 + 2], L[u * 4 + 3]), aL);
                aH = f2fma(g, dot8c(p0p, H[u * 4], H[u * 4 + 1], H[u * 4 + 2], H[u * 4 + 3]), aH);
            }
            #pragma unroll
            for (int u = 0; u < 16; ++u) {
                ulonglong2 l0 = L[64 + u * 2], l1 = L[64 + u * 2 + 1];
                ulonglong2 h0 = H[64 + u * 2], h1 = H[64 + u * 2 + 1];
                ull g = pk2(x0[u]);
                ull tL = f2mul(rp[0], l0.x);
                tL = f2fma(rp[1], l0.y, tL); tL = f2fma(rp[2], l1.x, tL); tL = f2fma(rp[3], l1.y, tL);
                ull tH = f2mul(rp[0], h0.x);
                tH = f2fma(rp[1], h0.y, tH); tH = f2fma(rp[2], h1.x, tH); tH = f2fma(rp[3], h1.y, tH);
                aL = f2fma(g, tL, aL); aH = f2fma(g, tH, aH);
            }
            #pragma unroll
            for (int u = 0; u < 8; ++u) {
                ull g = pk2(dd[u]);
                aL = f2fma(g, dot8c(p0p, L[112 + u * 4], L[112 + u * 4 + 1],
                                    L[112 + u * 4 + 2], L[112 + u * 4 + 3]), aL);
                aH = f2fma(g, dot8c(p0p, H[112 + u * 4], H[112 + u * 4 + 1],
                                    H[112 + u * 4 + 2], H[112 + u * 4 + 3]), aH);
            }
            float s3 = 0.f;
            const float4* mL = reinterpret_cast<const float4*>(sM + 384);
            const float4* mH = mL + 144;
            #pragma unroll
            for (int u = 0; u < 8; ++u) {
                float4 AL = mL[u * 2], BL = mL[u * 2 + 1];
                float4 AH = mH[u * 2], BH = mH[u * 2 + 1];
                float m0 = fmaf(f, AH.x, omf * AL.x), m1 = fmaf(f, AH.y, omf * AL.y);
                float m2 = fmaf(f, AH.z, omf * AL.z), m3 = fmaf(f, AH.w, omf * AL.w);
                float m4 = fmaf(f, BH.x, omf * BL.x), m5 = fmaf(f, BH.y, omf * BL.y);
                float m6 = fmaf(f, BH.z, omf * BL.z), m7 = fmaf(f, BH.w, omf * BL.w);
                float tvx = m0 * p1[0] + m1 * p1[3] + m2 * p1[6] + m3 * p1[9]
                          + m4 * p1[12] + m5 * p1[15] + m6 * p1[18] + m7 * p1[21];
                float tvy = m0 * p1[1] + m1 * p1[4] + m2 * p1[7] + m3 * p1[10]
                          + m4 * p1[13] + m5 * p1[16] + m6 * p1[19] + m7 * p1[22];
                float tvz = m0 * p1[2] + m1 * p1[5] + m2 * p1[8] + m3 * p1[11]
                          + m4 * p1[14] + m5 * p1[17] + m6 * p1[20] + m7 * p1[23];
                s3 += x1s[3 * u] * tvx + x1s[3 * u + 1] * tvy + x1s[3 * u + 2] * tvz;
            }
            float2 a2L = upk(aL), a2H = upk(aH);
            float score = ((a2L.x + a2L.y) * omf + (a2H.x + a2H.y) * f + s3) * 0.0028527222f;
            float tc = 10.0f * (1.0f - d * 0.125f);
            float cut = (tc > 0.f) ? __expf(-__frcp_rn(tc)) : 0.f;
            ev = cut * __expf(score);
        }
        atomicAdd(&g_z[dst], ev);
        float fs = sqrtf(ev) * 0.0510310363f;  // sqrt(ev)/(4*sqrt(24))

        // ---- value: blend-on-load from smem
        const ulonglong2* L = reinterpret_cast<const ulonglong2*>(sM + 1152);
        const ulonglong2* H = L + 144;
        ull o0p[8];
        #pragma unroll
        for (int k = 0; k < 8; ++k) o0p[k] = pk2(0.f);
        #pragma unroll
        for (int u = 0; u < 16; ++u) {
            ulonglong2 l0 = L[u * 4], l1 = L[u * 4 + 1], l2 = L[u * 4 + 2], l3 = L[u * 4 + 3];
            ulonglong2 h0 = H[u * 4], h1 = H[u * 4 + 1], h2 = H[u * 4 + 2], h3 = H[u * 4 + 3];
            ull g = pk2(x0[u] * sh.x);
            o0p[0] = f2fma(g, f2fma(fp, h0.x, f2mul(omfp, l0.x)), o0p[0]);
            o0p[1] = f2fma(g, f2fma(fp, h0.y, f2mul(omfp, l0.y)), o0p[1]);
            o0p[2] = f2fma(g, f2fma(fp, h1.x, f2mul(omfp, l1.x)), o0p[2]);
            o0p[3] = f2fma(g, f2fma(fp, h1.y, f2mul(omfp, l1.y)), o0p[3]);
            o0p[4] = f2fma(g, f2fma(fp, h2.x, f2mul(omfp, l2.x)), o0p[4]);
            o0p[5] = f2fma(g, f2fma(fp, h2.y, f2mul(omfp, l2.y)), o0p[5]);
            o0p[6] = f2fma(g, f2fma(fp, h3.x, f2mul(omfp, l3.x)), o0p[6]);
            o0p[7] = f2fma(g, f2fma(fp, h3.y, f2mul(omfp, l3.y)), o0p[7]);
        }
        #pragma unroll
        for (int u = 0; u < 8; ++u) {
            ulonglong2 l0 = L[112 + u * 4], l1 = L[112 + u * 4 + 1],
                       l2 = L[112 + u * 4 + 2], l3 = L[112 + u * 4 + 3];
            ulonglong2 h0 = H[112 + u * 4], h1 = H[112 + u * 4 + 1],
                       h2 = H[112 + u * 4 + 2], h3 = H[112 + u * 4 + 3];
            ull g = pk2(dd[u]);
            o0p[0] = f2fma(g, f2fma(fp, h0.x, f2mul(omfp, l0.x)), o0p[0]);
            o0p[1] = f2fma(g, f2fma(fp, h0.y, f2mul(omfp, l0.y)), o0p[1]);
            o0p[2] = f2fma(g, f2fma(fp, h1.x, f2mul(omfp, l1.x)), o0p[2]);
            o0p[3] = f2fma(g, f2fma(fp, h1.y, f2mul(omfp, l1.y)), o0p[3]);
            o0p[4] = f2fma(g, f2fma(fp, h2.x, f2mul(omfp, l2.x)), o0p[4]);
            o0p[5] = f2fma(g, f2fma(fp, h2.y, f2mul(omfp, l2.y)), o0p[5]);
            o0p[6] = f2fma(g, f2fma(fp, h3.x, f2mul(omfp, l3.x)), o0p[6]);
            o0p[7] = f2fma(g, f2fma(fp, h3.y, f2mul(omfp, l3.y)), o0p[7]);
        }
        ull Ap[4];
        #pragma unroll
        for (int k = 0; k < 4; ++k) Ap[k] = pk2(0.f);
        #pragma unroll
        for (int u = 0; u < 16; ++u) {
            ulonglong2 l0 = L[64 + u * 2], l1 = L[64 + u * 2 + 1];
            ulonglong2 h0 = H[64 + u * 2], h1 = H[64 + u * 2 + 1];
            ull g = pk2(x0[u]);
            Ap[0] = f2fma(g, f2fma(fp, h0.x, f2mul(omfp, l0.x)), Ap[0]);
            Ap[1] = f2fma(g, f2fma(fp, h0.y, f2mul(omfp, l0.y)), Ap[1]);
            Ap[2] = f2fma(g, f2fma(fp, h1.x, f2mul(omfp, l1.x)), Ap[2]);
            Ap[3] = f2fma(g, f2fma(fp, h1.y, f2mul(omfp, l1.y)), Ap[3]);
        }
        float o1[24];
        #pragma unroll
        for (int k = 0; k < 24; ++k) o1[k] = 0.f;
        {
            const float4* mL = reinterpret_cast<const float4*>(sM + 1152 + 384);
            const float4* mH = mL + 144;
            #pragma unroll
            for (int u = 0; u < 8; ++u) {
                float4 AL = mL[u * 2], BL = mL[u * 2 + 1];
                float4 AH = mH[u * 2], BH = mH[u * 2 + 1];
                float m0 = fmaf(f, AH.x, omf * AL.x), m1 = fmaf(f, AH.y, omf * AL.y);
                float m2 = fmaf(f, AH.z, omf * AL.z), m3 = fmaf(f, AH.w, omf * AL.w);
                float m4 = fmaf(f, BH.x, omf * BL.x), m5 = fmaf(f, BH.y, omf * BL.y);
                float m6 = fmaf(f, BH.z, omf * BL.z), m7 = fmaf(f, BH.w, omf * BL.w);
                float xa = x1s[3 * u], xb = x1s[3 * u + 1], xc = x1s[3 * u + 2];
                o1[0] = fmaf(m0, xa, o1[0]);  o1[1] = fmaf(m0, xb, o1[1]);  o1[2] = fmaf(m0, xc, o1[2]);
                o1[3] = fmaf(m1, xa, o1[3]);  o1[4] = fmaf(m1, xb, o1[4]);  o1[5] = fmaf(m1, xc, o1[5]);
                o1[6] = fmaf(m2, xa, o1[6]);  o1[7] = fmaf(m2, xb, o1[7]);  o1[8] = fmaf(m2, xc, o1[8]);
                o1[9] = fmaf(m3, xa, o1[9]);  o1[10] = fmaf(m3, xb, o1[10]); o1[11] = fmaf(m3, xc, o1[11]);
                o1[12] = fmaf(m4, xa, o1[12]); o1[13] = fmaf(m4, xb, o1[13]); o1[14] = fmaf(m4, xc, o1[14]);
                o1[15] = fmaf(m5, xa, o1[15]); o1[16] = fmaf(m5, xb, o1[16]); o1[17] = fmaf(m5, xc, o1[17]);
                o1[18] = fmaf(m6, xa, o1[18]); o1[19] = fmaf(m6, xb, o1[19]); o1[20] = fmaf(m6, xc, o1[20]);
                o1[21] = fmaf(m7, xa, o1[21]); o1[22] = fmaf(m7, xb, o1[22]); o1[23] = fmaf(m7, xc, o1[23]);
            }
        }
        #pragma unroll
        for (int k = 0; k < 4; ++k) {
            float2 a2 = upk(Ap[k]);
            int w0 = 2 * k, w1 = 2 * k + 1;
            o1[3 * w0] = fmaf(a2.x, sh.y, o1[3 * w0]);
            o1[3 * w0 + 1] = fmaf(a2.x, sh.z, o1[3 * w0 + 1]);
            o1[3 * w0 + 2] = fmaf(a2.x, sh.w, o1[3 * w0 + 2]);
            o1[3 * w1] = fmaf(a2.y, sh.y, o1[3 * w1]);
            o1[3 * w1 + 1] = fmaf(a2.y, sh.z, o1[3 * w1 + 1]);
            o1[3 * w1 + 2] = fmaf(a2.y, sh.w, o1[3 * w1 + 2]);
        }

        // ---- vectorized scatter: 10 x red.v4
        float* ob = out + dst * 40;
        float o0[16];
        #pragma unroll
        for (int k = 0; k < 8; ++k) {
            float2 q = upk(o0p[k]);
            o0[2 * k] = q.x * fs;
            o0[2 * k + 1] = q.y * fs;
        }
        #pragma unroll
        for (int k = 0; k < 4; ++k)
            red4(ob + 4 * k, o0[4 * k], o0[4 * k + 1], o0[4 * k + 2], o0[4 * k + 3]);
        #pragma unroll
        for (int k = 0; k < 6; ++k)
            red4(ob + 16 + 4 * k, o1[4 * k] * fs, o1[4 * k + 1] * fs,
                 o1[4 * k + 2] * fs, o1[4 * k + 3] * fs);
    }
}

// -------- epilogue: out[i] *= rsqrt(z[i]); re-zero g_cnt for next launch
__global__ void normalize(float* __restrict__ out, int n) {
    int i = blockIdx.x * 128 + threadIdx.x;
    if (i < TBLM) g_cnt[i] = 0;
    if (i >= n) return;
    float zz = g_z[i];
    if (zz <= 0.f) zz = 1.f;
    float s = rsqrtf(zz);
    float4* o4 = reinterpret_cast<float4*>(out + i * 40);
    #pragma unroll
    for (int m = 0; m < 10; ++m) {
        float4 v = o4[m];
        v.x *= s; v.y *= s; v.z *= s; v.w *= s;
        o4[m] = v;
    }
}

extern "C" void kernel_launch(void* const* d_in, const int* in_sizes, int n_in,
                              void* d_out, int out_size) {
    const float* x   = (const float*)d_in[0];
    const int*   ei  = (const int*)d_in[1];
    const float* ea  = (const float*)d_in[2];
    const float* amf = (const float*)d_in[5];
    const float* Wq0 = (const float*)d_in[6];
    const float* Wq1 = (const float*)d_in[7];
    const float* Wk1 = (const float*)d_in[8];
    const float* Wk2 = (const float*)d_in[9];
    const float* Wv1 = (const float*)d_in[10];
    const float* Wv2 = (const float*)d_in[11];
    const float* Wd0 = (const float*)d_in[12];
    const float* Wd1 = (const float*)d_in[13];
    float* out = (float*)d_out;

    int n = in_sizes[0] / 40;
    int E = in_sizes[2] / 4;

    build_h_hist<<<(E + 255) / 256, 256>>>(Wk1, Wv1, amf, E);
    scan_kernel<<<1, 1024>>>(TBLM);
    int nbScat = (E + 255) / 256;
    int nbNode = (n + 255) / 256;
    int nbM = ((TBLM + 1) * 288 + 255) / 256;
    mega_kernel<<<nbScat + nbNode + nbM, 256>>>(
        x, ei, ea, amf, Wq0, Wq1, Wd0, Wd1, Wk2, Wv2, out, n, E, nbScat, nbNode);
    edge_fused<<<TBLM, 96>>>(x, out, E);
    normalize<<<(n + 127) / 128, 128>>>(out, n);
}